// round 1
// baseline (speedup 1.0000x reference)
#include <cuda_runtime.h>
#include <math.h>

// Problem constants (static in the reference)
#define EMBED   256
#define HEADS   8
#define LEVELS  3
#define POINTS  4
#define DHEAD   32
#define BATCH   2
#define SEQ     21504          // 128*128 + 64*64 + 32*32
#define NQUERY  21504
#define MROWS   (BATCH * NQUERY)   // 43008

// Scratch (device globals; no allocation allowed)
__device__ float g_value[(size_t)BATCH * SEQ * EMBED];                   // [B,S,H,D]
__device__ float g_off  [(size_t)MROWS * HEADS * LEVELS * POINTS * 2];   // [B*Q,192]
__device__ float g_aw   [(size_t)MROWS * HEADS * LEVELS * POINTS];       // [B*Q,96]
__device__ float g_msda [(size_t)MROWS * EMBED];                         // [B*Q,256]

// ---------------------------------------------------------------------------
// SGEMM: C[M,N] = A[M,K] * W[N,K]^T + bias[N]
// BM=128, BN=64, BK=16, 256 threads, 8x4 per thread.
// M assumed multiple of 128 (43008 = 336*128). N guarded.
// ---------------------------------------------------------------------------
__global__ void __launch_bounds__(256) sgemm_wt_bias(
    const float* __restrict__ A, const float* __restrict__ W,
    const float* __restrict__ bias, float* __restrict__ C,
    int M, int N, int K)
{
    const int BM = 128, BN = 64, BK = 16;
    __shared__ float As[16][BM + 1];   // transposed tiles, +1 pad
    __shared__ float Ws[16][BN + 1];

    const int tid = threadIdx.x;
    const int tx  = tid & 15;          // N direction (4 cols each)
    const int ty  = tid >> 4;          // M direction (8 rows each)
    const int m0  = blockIdx.y * BM;
    const int n0  = blockIdx.x * BN;

    float acc[8][4];
#pragma unroll
    for (int i = 0; i < 8; i++)
#pragma unroll
        for (int j = 0; j < 4; j++) acc[i][j] = 0.f;

    const int lrow = tid >> 2;   // 0..63
    const int lkq  = tid & 3;    // 0..3 -> k offset lkq*4

    for (int k0 = 0; k0 < K; k0 += BK) {
        // A tile: rows lrow and lrow+64
#pragma unroll
        for (int r = 0; r < 2; r++) {
            int row = lrow + r * 64;
            float4 v = *reinterpret_cast<const float4*>(
                &A[(size_t)(m0 + row) * K + k0 + lkq * 4]);
            As[lkq * 4 + 0][row] = v.x;
            As[lkq * 4 + 1][row] = v.y;
            As[lkq * 4 + 2][row] = v.z;
            As[lkq * 4 + 3][row] = v.w;
        }
        // W tile: row lrow (0..63)
        {
            int wn = n0 + lrow;
            float4 v = make_float4(0.f, 0.f, 0.f, 0.f);
            if (wn < N)
                v = *reinterpret_cast<const float4*>(
                    &W[(size_t)wn * K + k0 + lkq * 4]);
            Ws[lkq * 4 + 0][lrow] = v.x;
            Ws[lkq * 4 + 1][lrow] = v.y;
            Ws[lkq * 4 + 2][lrow] = v.z;
            Ws[lkq * 4 + 3][lrow] = v.w;
        }
        __syncthreads();

#pragma unroll
        for (int kk = 0; kk < BK; kk++) {
            float a[8], b[4];
#pragma unroll
            for (int i = 0; i < 8; i++) a[i] = As[kk][ty * 8 + i];
#pragma unroll
            for (int j = 0; j < 4; j++) b[j] = Ws[kk][tx * 4 + j];
#pragma unroll
            for (int i = 0; i < 8; i++)
#pragma unroll
                for (int j = 0; j < 4; j++)
                    acc[i][j] = fmaf(a[i], b[j], acc[i][j]);
        }
        __syncthreads();
    }

#pragma unroll
    for (int i = 0; i < 8; i++) {
        int m = m0 + ty * 8 + i;
#pragma unroll
        for (int j = 0; j < 4; j++) {
            int n = n0 + tx * 4 + j;
            if (n < N)
                C[(size_t)m * N + n] = acc[i][j] + bias[n];
        }
    }
}

// ---------------------------------------------------------------------------
// Deformable sampling: one warp per (b, q, h); lane = channel d (0..31).
// value layout [B,S,H,D]; output g_msda[b*Q+q][h*32+d].
// ---------------------------------------------------------------------------
__global__ void __launch_bounds__(256) msda_sample_kernel(
    const float* __restrict__ refp)
{
    const int gwarp = (blockIdx.x * blockDim.x + threadIdx.x) >> 5;
    const int lane  = threadIdx.x & 31;

    const int h  = gwarp & (HEADS - 1);
    const int bq = gwarp >> 3;
    if (bq >= MROWS) return;
    const int b = bq / NQUERY;

    // softmax over 12 attention logits (broadcast loads across the warp)
    const float* awp = g_aw + (size_t)bq * (HEADS * LEVELS * POINTS) + h * (LEVELS * POINTS);
    float w[12];
    float mx = -1e30f;
#pragma unroll
    for (int j = 0; j < 12; j++) { w[j] = awp[j]; mx = fmaxf(mx, w[j]); }
    float s = 0.f;
#pragma unroll
    for (int j = 0; j < 12; j++) { w[j] = __expf(w[j] - mx); s += w[j]; }
    const float invs = 1.f / s;

    const float* offp = g_off + (size_t)bq * (HEADS * LEVELS * POINTS * 2)
                              + h * (LEVELS * POINTS * 2);
    const float* rp = refp + (size_t)bq * LEVELS * 2;

    const int lvlW[3]     = {128, 64, 32};
    const int lvlStart[3] = {0, 16384, 20480};

    float acc = 0.f;
#pragma unroll
    for (int l = 0; l < LEVELS; l++) {
        const int   Wl = lvlW[l];
        const int   Hl = Wl;
        const float fW = (float)Wl;
        const float fH = (float)Hl;
        const float rx = rp[l * 2 + 0];
        const float ry = rp[l * 2 + 1];
        const float* base = g_value
            + ((size_t)(b * SEQ + lvlStart[l]) * HEADS + h) * DHEAD + lane;
#pragma unroll
        for (int p = 0; p < POINTS; p++) {
            float ox = offp[(l * POINTS + p) * 2 + 0];
            float oy = offp[(l * POINTS + p) * 2 + 1];
            // (ref + off/W)*W - 0.5 == ref*W + off - 0.5  (W,H are powers of 2)
            float x = fmaf(rx, fW, ox) - 0.5f;
            float y = fmaf(ry, fH, oy) - 0.5f;
            float xf = floorf(x), yf = floorf(y);
            float wx = x - xf,    wy = y - yf;
            int   x0 = (int)xf,   y0 = (int)yf;

            bool xv0 = (x0 >= 0)     && (x0 < Wl);
            bool xv1 = (x0 + 1 >= 0) && (x0 + 1 < Wl);
            bool yv0 = (y0 >= 0)     && (y0 < Hl);
            bool yv1 = (y0 + 1 >= 0) && (y0 + 1 < Hl);

            float v00 = 0.f, v01 = 0.f, v10 = 0.f, v11 = 0.f;
            if (yv0) {
                int r0 = y0 * Wl;
                if (xv0) v00 = base[(size_t)(r0 + x0) * (HEADS * DHEAD)];
                if (xv1) v01 = base[(size_t)(r0 + x0 + 1) * (HEADS * DHEAD)];
            }
            if (yv1) {
                int r1 = (y0 + 1) * Wl;
                if (xv0) v10 = base[(size_t)(r1 + x0) * (HEADS * DHEAD)];
                if (xv1) v11 = base[(size_t)(r1 + x0 + 1) * (HEADS * DHEAD)];
            }
            float bil = (1.f - wx) * (1.f - wy) * v00
                      +        wx  * (1.f - wy) * v01
                      + (1.f - wx) *        wy  * v10
                      +        wx  *        wy  * v11;
            acc = fmaf(w[l * POINTS + p] * invs, bil, acc);
        }
    }
    g_msda[((size_t)bq * HEADS + h) * DHEAD + lane] = acc;
}

// ---------------------------------------------------------------------------

extern "C" void kernel_launch(void* const* d_in, const int* in_sizes, int n_in,
                              void* d_out, int out_size)
{
    const float* hidden = (const float*)d_in[0];   // [B,Q,256]
    const float* enc    = (const float*)d_in[1];   // [B,S,256]
    const float* refp   = (const float*)d_in[2];   // [B,Q,L,2]
    // d_in[3] = spatial_shapes (static, hardcoded)
    const float* off_w  = (const float*)d_in[4];   // [192,256]
    const float* off_b  = (const float*)d_in[5];
    const float* aw_w   = (const float*)d_in[6];   // [96,256]
    const float* aw_b   = (const float*)d_in[7];
    const float* val_w  = (const float*)d_in[8];   // [256,256]
    const float* val_b  = (const float*)d_in[9];
    const float* out_w  = (const float*)d_in[10];  // [256,256]
    const float* out_b  = (const float*)d_in[11];
    float* out = (float*)d_out;

    float *p_value, *p_off, *p_aw, *p_msda;
    cudaGetSymbolAddress((void**)&p_value, g_value);
    cudaGetSymbolAddress((void**)&p_off,   g_off);
    cudaGetSymbolAddress((void**)&p_aw,    g_aw);
    cudaGetSymbolAddress((void**)&p_msda,  g_msda);

    const int M = MROWS, K = EMBED;
    dim3 blk(256);

    // value projection: [B*S,256] @ [256,256]^T
    sgemm_wt_bias<<<dim3(EMBED / 64, M / 128), blk>>>(enc, val_w, val_b, p_value, M, EMBED, K);
    // sampling offsets: N=192
    sgemm_wt_bias<<<dim3(192 / 64, M / 128), blk>>>(hidden, off_w, off_b, p_off, M, 192, K);
    // attention weights: N=96 -> 2 blocks of 64 with guard
    sgemm_wt_bias<<<dim3(2, M / 128), blk>>>(hidden, aw_w, aw_b, p_aw, M, 96, K);

    // deformable sampling: one warp per (b,q,h)
    const int nwarps = MROWS * HEADS;            // 344064
    msda_sample_kernel<<<nwarps / 8, 256>>>(refp);

    // output projection
    sgemm_wt_bias<<<dim3(EMBED / 64, M / 128), blk>>>(p_msda, out_w, out_b, out, M, EMBED, K);
}

// round 2
// speedup vs baseline: 2.5556x; 2.5556x over previous
#include <cuda_runtime.h>
#include <math.h>

// Problem constants (static in the reference)
#define EMBED   256
#define HEADS   8
#define LEVELS  3
#define POINTS  4
#define DHEAD   32
#define BATCH   2
#define SEQ     21504          // 128*128 + 64*64 + 32*32
#define NQUERY  21504
#define MROWS   (BATCH * NQUERY)   // 43008

// Scratch (device globals; no allocation allowed)
__device__ float g_value[(size_t)BATCH * SEQ * EMBED];                   // [B,S,H,D]
__device__ float g_off  [(size_t)MROWS * HEADS * LEVELS * POINTS * 2];   // [B*Q,192]
__device__ float g_aw   [(size_t)MROWS * HEADS * LEVELS * POINTS];       // [B*Q,96]
__device__ float g_msda [(size_t)MROWS * EMBED];                         // [B*Q,256]

__device__ __forceinline__ unsigned f2tf32(float f) {
    unsigned u;
    asm("cvt.rna.tf32.f32 %0, %1;" : "=r"(u) : "f"(f));
    return u;
}

// ---------------------------------------------------------------------------
// TF32 tensor-core GEMM: C[M,N] = A[M,256] * W[N,256]^T + bias[N]
// BM=128, BN=64, BK=32; 256 threads = 8 warps (4 m x 2 n), warp tile 32x32,
// mma.sync.m16n8k8 tf32. M must be a multiple of 128. N guarded.
// ---------------------------------------------------------------------------
__global__ void __launch_bounds__(256) mma_gemm_wt_bias(
    const float* __restrict__ A, const float* __restrict__ W,
    const float* __restrict__ bias, float* __restrict__ C, int N)
{
    const int K = 256;
    __shared__ unsigned As[128][36];   // [m][k] tf32 bits, pad->stride 36
    __shared__ unsigned Ws[64][36];    // [n][k]

    const int tid  = threadIdx.x;
    const int wid  = tid >> 5;
    const int lane = tid & 31;
    const int g    = lane >> 2;     // group id 0..7
    const int t    = lane & 3;      // thread-in-group 0..3

    const int m0 = blockIdx.y * 128;
    const int n0 = blockIdx.x * 64;
    const int warp_m = (wid & 3) * 32;
    const int warp_n = (wid >> 2) * 32;

    float acc[2][4][4];
#pragma unroll
    for (int mi = 0; mi < 2; mi++)
#pragma unroll
        for (int ni = 0; ni < 4; ni++)
#pragma unroll
            for (int c = 0; c < 4; c++) acc[mi][ni][c] = 0.f;

    for (int k0 = 0; k0 < K; k0 += 32) {
        // stage global loads in registers (overlaps with previous compute)
        float4 av[4];
#pragma unroll
        for (int i = 0; i < 4; i++) {
            int idx = tid + i * 256;            // 0..1023
            int row = idx >> 3;                 // 0..127
            int c4  = idx & 7;                  // 0..7
            av[i] = *reinterpret_cast<const float4*>(
                &A[(size_t)(m0 + row) * K + k0 + c4 * 4]);
        }
        float4 wv[2];
#pragma unroll
        for (int i = 0; i < 2; i++) {
            int idx = tid + i * 256;            // 0..511
            int row = idx >> 3;                 // 0..63
            int c4  = idx & 7;
            int n   = n0 + row;
            wv[i] = (n < N) ? *reinterpret_cast<const float4*>(
                                  &W[(size_t)n * K + k0 + c4 * 4])
                            : make_float4(0.f, 0.f, 0.f, 0.f);
        }
        __syncthreads();
#pragma unroll
        for (int i = 0; i < 4; i++) {
            int idx = tid + i * 256;
            int row = idx >> 3, c4 = idx & 7;
            As[row][c4 * 4 + 0] = f2tf32(av[i].x);
            As[row][c4 * 4 + 1] = f2tf32(av[i].y);
            As[row][c4 * 4 + 2] = f2tf32(av[i].z);
            As[row][c4 * 4 + 3] = f2tf32(av[i].w);
        }
#pragma unroll
        for (int i = 0; i < 2; i++) {
            int idx = tid + i * 256;
            int row = idx >> 3, c4 = idx & 7;
            Ws[row][c4 * 4 + 0] = f2tf32(wv[i].x);
            Ws[row][c4 * 4 + 1] = f2tf32(wv[i].y);
            Ws[row][c4 * 4 + 2] = f2tf32(wv[i].z);
            Ws[row][c4 * 4 + 3] = f2tf32(wv[i].w);
        }
        __syncthreads();

#pragma unroll
        for (int kk = 0; kk < 4; kk++) {
            const int kb = kk * 8;
            unsigned a[2][4], b[4][2];
#pragma unroll
            for (int mi = 0; mi < 2; mi++) {
                int rm = warp_m + mi * 16;
                a[mi][0] = As[rm + g    ][kb + t    ];
                a[mi][1] = As[rm + g + 8][kb + t    ];
                a[mi][2] = As[rm + g    ][kb + t + 4];
                a[mi][3] = As[rm + g + 8][kb + t + 4];
            }
#pragma unroll
            for (int ni = 0; ni < 4; ni++) {
                int rn = warp_n + ni * 8 + g;
                b[ni][0] = Ws[rn][kb + t    ];
                b[ni][1] = Ws[rn][kb + t + 4];
            }
#pragma unroll
            for (int mi = 0; mi < 2; mi++)
#pragma unroll
                for (int ni = 0; ni < 4; ni++) {
                    asm volatile(
                        "mma.sync.aligned.m16n8k8.row.col.f32.tf32.tf32.f32 "
                        "{%0,%1,%2,%3}, {%4,%5,%6,%7}, {%8,%9}, {%0,%1,%2,%3};"
                        : "+f"(acc[mi][ni][0]), "+f"(acc[mi][ni][1]),
                          "+f"(acc[mi][ni][2]), "+f"(acc[mi][ni][3])
                        : "r"(a[mi][0]), "r"(a[mi][1]), "r"(a[mi][2]), "r"(a[mi][3]),
                          "r"(b[ni][0]), "r"(b[ni][1]));
                }
        }
    }

    // epilogue
#pragma unroll
    for (int mi = 0; mi < 2; mi++) {
        int row0 = m0 + warp_m + mi * 16 + g;
#pragma unroll
        for (int ni = 0; ni < 4; ni++) {
            int col = n0 + warp_n + ni * 8 + t * 2;
            if (col < N) {
                float bx = bias[col], by = bias[col + 1];
                float2 v0 = make_float2(acc[mi][ni][0] + bx, acc[mi][ni][1] + by);
                float2 v1 = make_float2(acc[mi][ni][2] + bx, acc[mi][ni][3] + by);
                *reinterpret_cast<float2*>(&C[(size_t)row0 * N + col]) = v0;
                *reinterpret_cast<float2*>(&C[(size_t)(row0 + 8) * N + col]) = v1;
            }
        }
    }
}

// ---------------------------------------------------------------------------
// Deformable sampling: one warp per (b, q, head-group-of-4).
// lane>>3 = head sub-index, lane&7 = channel group (float4).
// value layout [B,S,H,D]; heads adjacent -> 512B contiguous per corner instr.
// ---------------------------------------------------------------------------
__global__ void __launch_bounds__(256) msda_sample_kernel(
    const float* __restrict__ refp)
{
    const int gwarp = (blockIdx.x * blockDim.x + threadIdx.x) >> 5;
    const int lane  = threadIdx.x & 31;

    const int bq = gwarp >> 1;
    if (bq >= MROWS) return;
    const int hg   = (gwarp & 1) * 4;         // head group base
    const int h    = hg + (lane >> 3);        // this lane's head
    const int cg   = lane & 7;                // channel group (4 floats)
    const int b    = (bq >= NQUERY) ? 1 : 0;

    // softmax over 12 attention logits for this lane's head
    const float* awp = g_aw + (size_t)bq * (HEADS * LEVELS * POINTS) + h * (LEVELS * POINTS);
    float w[12];
    float mx = -1e30f;
#pragma unroll
    for (int j = 0; j < 12; j++) { w[j] = awp[j]; mx = fmaxf(mx, w[j]); }
    float s = 0.f;
#pragma unroll
    for (int j = 0; j < 12; j++) { w[j] = __expf(w[j] - mx); s += w[j]; }
    const float invs = 1.f / s;

    const float* offp = g_off + (size_t)bq * (HEADS * LEVELS * POINTS * 2)
                              + h * (LEVELS * POINTS * 2);
    const float* rp = refp + (size_t)bq * LEVELS * 2;

    const int lvlW[3]     = {128, 64, 32};
    const int lvlStart[3] = {0, 16384, 20480};

    float4 acc = make_float4(0.f, 0.f, 0.f, 0.f);
#pragma unroll
    for (int l = 0; l < LEVELS; l++) {
        const int   Wl = lvlW[l];
        const float fW = (float)Wl;
        const float rx = rp[l * 2 + 0];
        const float ry = rp[l * 2 + 1];
        // pixel stride = HEADS*DHEAD floats = 64 float4
        const float4* base = reinterpret_cast<const float4*>(
            g_value + ((size_t)(b * SEQ + lvlStart[l]) * HEADS + h) * DHEAD) + cg;
#pragma unroll
        for (int p = 0; p < POINTS; p++) {
            float ox = offp[(l * POINTS + p) * 2 + 0];
            float oy = offp[(l * POINTS + p) * 2 + 1];
            // (ref + off/W)*W - 0.5 == ref*W + off - 0.5 (square levels)
            float x = fmaf(rx, fW, ox) - 0.5f;
            float y = fmaf(ry, fW, oy) - 0.5f;
            float xf = floorf(x), yf = floorf(y);
            float wx = x - xf,    wy = y - yf;
            int   x0 = (int)xf,   y0 = (int)yf;

            bool xv0 = (x0 >= 0)     && (x0 < Wl);
            bool xv1 = (x0 >= -1)    && (x0 < Wl - 1);
            bool yv0 = (y0 >= 0)     && (y0 < Wl);
            bool yv1 = (y0 >= -1)    && (y0 < Wl - 1);

            float4 v00 = make_float4(0.f,0.f,0.f,0.f), v01 = v00, v10 = v00, v11 = v00;
            if (yv0) {
                size_t r0 = (size_t)(y0 * Wl) * 64;
                if (xv0) v00 = base[r0 + (size_t)x0 * 64];
                if (xv1) v01 = base[r0 + (size_t)(x0 + 1) * 64];
            }
            if (yv1) {
                size_t r1 = (size_t)((y0 + 1) * Wl) * 64;
                if (xv0) v10 = base[r1 + (size_t)x0 * 64];
                if (xv1) v11 = base[r1 + (size_t)(x0 + 1) * 64];
            }
            float w00 = (1.f - wx) * (1.f - wy);
            float w01 =        wx  * (1.f - wy);
            float w10 = (1.f - wx) *        wy;
            float w11 =        wx  *        wy;
            float ws  = w[l * POINTS + p] * invs;

            float bx = v00.x * w00 + v01.x * w01 + v10.x * w10 + v11.x * w11;
            float by = v00.y * w00 + v01.y * w01 + v10.y * w10 + v11.y * w11;
            float bz = v00.z * w00 + v01.z * w01 + v10.z * w10 + v11.z * w11;
            float bw = v00.w * w00 + v01.w * w01 + v10.w * w10 + v11.w * w11;
            acc.x = fmaf(ws, bx, acc.x);
            acc.y = fmaf(ws, by, acc.y);
            acc.z = fmaf(ws, bz, acc.z);
            acc.w = fmaf(ws, bw, acc.w);
        }
    }
    float4* outp = reinterpret_cast<float4*>(
        g_msda + ((size_t)bq * HEADS + h) * DHEAD) + cg;
    *outp = acc;
}

// ---------------------------------------------------------------------------

extern "C" void kernel_launch(void* const* d_in, const int* in_sizes, int n_in,
                              void* d_out, int out_size)
{
    const float* hidden = (const float*)d_in[0];   // [B,Q,256]
    const float* enc    = (const float*)d_in[1];   // [B,S,256]
    const float* refp   = (const float*)d_in[2];   // [B,Q,L,2]
    // d_in[3] = spatial_shapes (static, hardcoded)
    const float* off_w  = (const float*)d_in[4];   // [192,256]
    const float* off_b  = (const float*)d_in[5];
    const float* aw_w   = (const float*)d_in[6];   // [96,256]
    const float* aw_b   = (const float*)d_in[7];
    const float* val_w  = (const float*)d_in[8];   // [256,256]
    const float* val_b  = (const float*)d_in[9];
    const float* out_w  = (const float*)d_in[10];  // [256,256]
    const float* out_b  = (const float*)d_in[11];
    float* out = (float*)d_out;

    float *p_value, *p_off, *p_aw, *p_msda;
    cudaGetSymbolAddress((void**)&p_value, g_value);
    cudaGetSymbolAddress((void**)&p_off,   g_off);
    cudaGetSymbolAddress((void**)&p_aw,    g_aw);
    cudaGetSymbolAddress((void**)&p_msda,  g_msda);

    const int MB = MROWS / 128;   // 336
    dim3 blk(256);

    // value projection: [B*S,256] @ [256,256]^T
    mma_gemm_wt_bias<<<dim3(4, MB), blk>>>(enc, val_w, val_b, p_value, 256);
    // sampling offsets: N=192
    mma_gemm_wt_bias<<<dim3(3, MB), blk>>>(hidden, off_w, off_b, p_off, 192);
    // attention weights: N=96
    mma_gemm_wt_bias<<<dim3(2, MB), blk>>>(hidden, aw_w, aw_b, p_aw, 96);

    // deformable sampling: one warp per (b,q,4-head group)
    const int nwarps = MROWS * 2;                 // 86016
    msda_sample_kernel<<<nwarps / 8, 256>>>(refp);

    // output projection
    mma_gemm_wt_bias<<<dim3(4, MB), blk>>>(p_msda, out_w, out_b, out, 256);
}

// round 3
// speedup vs baseline: 2.7899x; 1.0917x over previous
#include <cuda_runtime.h>
#include <math.h>

// Problem constants (static in the reference)
#define EMBED   256
#define HEADS   8
#define LEVELS  3
#define POINTS  4
#define DHEAD   32
#define BATCH   2
#define SEQ     21504          // 128*128 + 64*64 + 32*32
#define NQUERY  21504
#define MROWS   (BATCH * NQUERY)   // 43008

// Scratch (device globals; no allocation allowed)
__device__ float g_value[(size_t)BATCH * SEQ * EMBED];                   // [B,S,H,D]
__device__ float g_off  [(size_t)MROWS * HEADS * LEVELS * POINTS * 2];   // [B*Q,192]
__device__ float g_aw   [(size_t)MROWS * HEADS * LEVELS * POINTS];       // [B*Q,96]
__device__ float g_msda [(size_t)MROWS * EMBED];                         // [B*Q,256]

__device__ __forceinline__ unsigned f2tf32(float f) {
    unsigned u;
    asm("cvt.rna.tf32.f32 %0, %1;" : "=r"(u) : "f"(f));
    return u;
}

__device__ __forceinline__ void cp_async16(unsigned smem_addr, const void* gptr, int src_size) {
    asm volatile("cp.async.cg.shared.global [%0], [%1], 16, %2;\n"
                 :: "r"(smem_addr), "l"(gptr), "r"(src_size));
}
__device__ __forceinline__ void cp_async_commit() {
    asm volatile("cp.async.commit_group;\n");
}

// ---------------------------------------------------------------------------
// TF32 tensor-core GEMM: C[M,N] = A[M,256] * W[N,256]^T + bias[N]
// BM=128, BN=64, BK=32; 256 threads = 8 warps (4 m x 2 n), warp tile 32x32.
// Double-buffered cp.async pipeline; XOR-swizzled smem (conflict-free LDS).
// M multiple of 128. N guarded (zero-filled via cp.async src_size=0).
// ---------------------------------------------------------------------------
__global__ void __launch_bounds__(256) mma_gemm_wt_bias(
    const float* __restrict__ A, const float* __restrict__ W,
    const float* __restrict__ bias, float* __restrict__ C, int N)
{
    const int K = 256;
    // [stage][row][8 chunks of float4], chunk stored at (c ^ (row&7))
    __shared__ float4 As4[2][128 * 8];
    __shared__ float4 Ws4[2][64 * 8];

    const int tid  = threadIdx.x;
    const int wid  = tid >> 5;
    const int lane = tid & 31;
    const int g    = lane >> 2;     // 0..7
    const int t    = lane & 3;      // 0..3

    const int m0 = blockIdx.y * 128;
    const int n0 = blockIdx.x * 64;
    const int warp_m = (wid & 3) * 32;
    const int warp_n = (wid >> 2) * 32;

    const float* As_f[2] = { (const float*)As4[0], (const float*)As4[1] };
    const float* Ws_f[2] = { (const float*)Ws4[0], (const float*)Ws4[1] };

    // cp.async staging indices (fixed per thread)
    const int a_row0 = tid >> 3;          // 0..31 step: +32 per rep (4 reps)
    const int a_c    = tid & 7;

    float acc[2][4][4];
#pragma unroll
    for (int mi = 0; mi < 2; mi++)
#pragma unroll
        for (int ni = 0; ni < 4; ni++)
#pragma unroll
            for (int c = 0; c < 4; c++) acc[mi][ni][c] = 0.f;

    auto load_stage = [&](int stage, int k0) {
        // A: 128 rows x 8 chunks = 1024 chunks, 4 per thread
#pragma unroll
        for (int i = 0; i < 4; i++) {
            int row = a_row0 + i * 32;
            int sw  = a_c ^ (row & 7);
            unsigned dst = (unsigned)__cvta_generic_to_shared(&As4[stage][row * 8 + sw]);
            cp_async16(dst, &A[(size_t)(m0 + row) * K + k0 + a_c * 4], 16);
        }
        // W: 64 rows x 8 chunks = 512 chunks, 2 per thread
#pragma unroll
        for (int i = 0; i < 2; i++) {
            int row = a_row0 + i * 32;      // 0..63
            int sw  = a_c ^ (row & 7);
            unsigned dst = (unsigned)__cvta_generic_to_shared(&Ws4[stage][row * 8 + sw]);
            int n = n0 + row;
            int ok = (n < N) ? 16 : 0;
            const float* src = (n < N) ? &W[(size_t)n * K + k0 + a_c * 4] : W;
            cp_async16(dst, src, ok);
        }
        cp_async_commit();
    };

    load_stage(0, 0);

    const int NIT = K / 32;   // 8
#pragma unroll 1
    for (int it = 0; it < NIT; it++) {
        const int cur = it & 1;
        if (it + 1 < NIT) {
            load_stage(cur ^ 1, (it + 1) * 32);
            asm volatile("cp.async.wait_group 1;\n");
        } else {
            asm volatile("cp.async.wait_group 0;\n");
        }
        __syncthreads();

        const float* Af = As_f[cur];
        const float* Wf = Ws_f[cur];
#pragma unroll
        for (int kk = 0; kk < 4; kk++) {
            const int kb = kk * 8;
            const int c0 = kb >> 2;        // chunk for k = kb+t
            const int c1 = c0 + 1;         // chunk for k = kb+4+t
            unsigned a[2][4], b[4][2];
#pragma unroll
            for (int mi = 0; mi < 2; mi++) {
                int r0 = warp_m + mi * 16 + g;
                int r1 = r0 + 8;
                a[mi][0] = f2tf32(Af[r0 * 32 + ((c0 ^ (r0 & 7)) << 2) + t]);
                a[mi][1] = f2tf32(Af[r1 * 32 + ((c0 ^ (r1 & 7)) << 2) + t]);
                a[mi][2] = f2tf32(Af[r0 * 32 + ((c1 ^ (r0 & 7)) << 2) + t]);
                a[mi][3] = f2tf32(Af[r1 * 32 + ((c1 ^ (r1 & 7)) << 2) + t]);
            }
#pragma unroll
            for (int ni = 0; ni < 4; ni++) {
                int rn = warp_n + ni * 8 + g;
                b[ni][0] = f2tf32(Wf[rn * 32 + ((c0 ^ (rn & 7)) << 2) + t]);
                b[ni][1] = f2tf32(Wf[rn * 32 + ((c1 ^ (rn & 7)) << 2) + t]);
            }
#pragma unroll
            for (int mi = 0; mi < 2; mi++)
#pragma unroll
                for (int ni = 0; ni < 4; ni++) {
                    asm volatile(
                        "mma.sync.aligned.m16n8k8.row.col.f32.tf32.tf32.f32 "
                        "{%0,%1,%2,%3}, {%4,%5,%6,%7}, {%8,%9}, {%0,%1,%2,%3};"
                        : "+f"(acc[mi][ni][0]), "+f"(acc[mi][ni][1]),
                          "+f"(acc[mi][ni][2]), "+f"(acc[mi][ni][3])
                        : "r"(a[mi][0]), "r"(a[mi][1]), "r"(a[mi][2]), "r"(a[mi][3]),
                          "r"(b[ni][0]), "r"(b[ni][1]));
                }
        }
        __syncthreads();
    }

    // epilogue
#pragma unroll
    for (int mi = 0; mi < 2; mi++) {
        int row0 = m0 + warp_m + mi * 16 + g;
#pragma unroll
        for (int ni = 0; ni < 4; ni++) {
            int col = n0 + warp_n + ni * 8 + t * 2;
            if (col < N) {
                float bx = bias[col], by = bias[col + 1];
                float2 v0 = make_float2(acc[mi][ni][0] + bx, acc[mi][ni][1] + by);
                float2 v1 = make_float2(acc[mi][ni][2] + bx, acc[mi][ni][3] + by);
                *reinterpret_cast<float2*>(&C[(size_t)row0 * N + col]) = v0;
                *reinterpret_cast<float2*>(&C[(size_t)(row0 + 8) * N + col]) = v1;
            }
        }
    }
}

// ---------------------------------------------------------------------------
// Deformable sampling, two-phase per block.
// Block = 8 queries x 8 heads. Phase 1: softmax + sample params (once per
// sample) into smem. Phase 2: pure gather (4x LDG.128 + FMA per sample).
// ---------------------------------------------------------------------------
#define QB 8
#define NSAMP (QB * HEADS * LEVELS * POINTS)   // 768

__global__ void __launch_bounds__(256) msda_sample_kernel(
    const float* __restrict__ refp)
{
    __shared__ float  s_aw[QB * HEADS * 12];   // normalized attn weights
    __shared__ int4   s_off[NSAMP];            // 4 corner offsets (float4 units)
    __shared__ float4 s_wt[NSAMP];             // premultiplied corner weights

    const int tid = threadIdx.x;
    const int bq0 = blockIdx.x * QB;

    // Phase 1a: softmax once per (q, h)
    if (tid < QB * HEADS) {
        const int bqi = tid >> 3;
        const int h   = tid & 7;
        const float* awp = g_aw + (size_t)(bq0 + bqi) * 96 + h * 12;
        float w[12];
        float mx = -1e30f;
#pragma unroll
        for (int j = 0; j < 12; j++) { w[j] = awp[j]; mx = fmaxf(mx, w[j]); }
        float s = 0.f;
#pragma unroll
        for (int j = 0; j < 12; j++) { w[j] = __expf(w[j] - mx); s += w[j]; }
        const float invs = 1.f / s;
#pragma unroll
        for (int j = 0; j < 12; j++) s_aw[tid * 12 + j] = w[j] * invs;
    }
    __syncthreads();

    // Phase 1b: per-sample params (3 samples per thread)
    const int lvlW[3]     = {128, 64, 32};
    const int lvlStart[3] = {0, 16384, 20480};
#pragma unroll
    for (int i = 0; i < 3; i++) {
        const int sid = tid + i * 256;         // 0..767
        const int bqi = sid / 96;
        const int r   = sid - bqi * 96;
        const int h   = r / 12;
        const int lp  = r - h * 12;
        const int l   = lp >> 2;

        const int bq = bq0 + bqi;
        const int b  = (bq >= NQUERY) ? 1 : 0;
        const int Wl = lvlW[l];
        const float fW = (float)Wl;

        const float ox = g_off[(size_t)bq * 192 + h * 24 + lp * 2 + 0];
        const float oy = g_off[(size_t)bq * 192 + h * 24 + lp * 2 + 1];
        const float rx = refp[(size_t)bq * 6 + l * 2 + 0];
        const float ry = refp[(size_t)bq * 6 + l * 2 + 1];

        const float x = fmaf(rx, fW, ox) - 0.5f;
        const float y = fmaf(ry, fW, oy) - 0.5f;
        const float xf = floorf(x), yf = floorf(y);
        const float wx = x - xf,    wy = y - yf;
        const int x0 = (int)xf, y0 = (int)yf;

        const bool vx0 = (x0 >= 0)  && (x0 < Wl);
        const bool vx1 = (x0 >= -1) && (x0 < Wl - 1);
        const bool vy0 = (y0 >= 0)  && (y0 < Wl);
        const bool vy1 = (y0 >= -1) && (y0 < Wl - 1);

        const int x0c = min(max(x0, 0), Wl - 1);
        const int x1c = min(max(x0 + 1, 0), Wl - 1);
        const int y0c = min(max(y0, 0), Wl - 1);
        const int y1c = min(max(y0 + 1, 0), Wl - 1);

        const float ws = s_aw[(bqi * 8 + h) * 12 + lp];
        float4 wt;
        wt.x = (vx0 && vy0) ? ws * (1.f - wx) * (1.f - wy) : 0.f;
        wt.y = (vx1 && vy0) ? ws *        wx  * (1.f - wy) : 0.f;
        wt.z = (vx0 && vy1) ? ws * (1.f - wx) *        wy  : 0.f;
        wt.w = (vx1 && vy1) ? ws *        wx  *        wy  : 0.f;

        // base in float4 units; pixel stride = 64 float4 (256 floats)
        const int base4 = ((b * SEQ + lvlStart[l]) * 8 + h) * 8;
        int4 off;
        off.x = base4 + (y0c * Wl + x0c) * 64;
        off.y = base4 + (y0c * Wl + x1c) * 64;
        off.z = base4 + (y1c * Wl + x0c) * 64;
        off.w = base4 + (y1c * Wl + x1c) * 64;

        s_off[sid] = off;
        s_wt[sid]  = wt;
    }
    __syncthreads();

    // Phase 2: gather. 64 units (bqi,h) x 8 lanes (cg), 2 passes.
    const float4* __restrict__ V4 = reinterpret_cast<const float4*>(g_value);
    const int cg = tid & 7;
#pragma unroll
    for (int pass = 0; pass < 2; pass++) {
        const int u   = (tid >> 3) + pass * 32;   // 0..63
        const int bqi = u >> 3;
        const int h   = u & 7;

        float4 acc = make_float4(0.f, 0.f, 0.f, 0.f);
#pragma unroll
        for (int s12 = 0; s12 < 12; s12++) {
            const int sid = u * 12 + s12;
            const int4   off = s_off[sid];
            const float4 wt  = s_wt[sid];
            const float4 v00 = V4[off.x + cg];
            const float4 v01 = V4[off.y + cg];
            const float4 v10 = V4[off.z + cg];
            const float4 v11 = V4[off.w + cg];
            acc.x += wt.x * v00.x + wt.y * v01.x + wt.z * v10.x + wt.w * v11.x;
            acc.y += wt.x * v00.y + wt.y * v01.y + wt.z * v10.y + wt.w * v11.y;
            acc.z += wt.x * v00.z + wt.y * v01.z + wt.z * v10.z + wt.w * v11.z;
            acc.w += wt.x * v00.w + wt.y * v01.w + wt.z * v10.w + wt.w * v11.w;
        }
        float4* outp = reinterpret_cast<float4*>(g_msda) + ((size_t)(bq0 + bqi) * 8 + h) * 8 + cg;
        *outp = acc;
    }
}

// ---------------------------------------------------------------------------

extern "C" void kernel_launch(void* const* d_in, const int* in_sizes, int n_in,
                              void* d_out, int out_size)
{
    const float* hidden = (const float*)d_in[0];   // [B,Q,256]
    const float* enc    = (const float*)d_in[1];   // [B,S,256]
    const float* refp   = (const float*)d_in[2];   // [B,Q,L,2]
    // d_in[3] = spatial_shapes (static, hardcoded)
    const float* off_w  = (const float*)d_in[4];   // [192,256]
    const float* off_b  = (const float*)d_in[5];
    const float* aw_w   = (const float*)d_in[6];   // [96,256]
    const float* aw_b   = (const float*)d_in[7];
    const float* val_w  = (const float*)d_in[8];   // [256,256]
    const float* val_b  = (const float*)d_in[9];
    const float* out_w  = (const float*)d_in[10];  // [256,256]
    const float* out_b  = (const float*)d_in[11];
    float* out = (float*)d_out;

    float *p_value, *p_off, *p_aw, *p_msda;
    cudaGetSymbolAddress((void**)&p_value, g_value);
    cudaGetSymbolAddress((void**)&p_off,   g_off);
    cudaGetSymbolAddress((void**)&p_aw,    g_aw);
    cudaGetSymbolAddress((void**)&p_msda,  g_msda);

    const int MB = MROWS / 128;   // 336
    dim3 blk(256);

    // value projection: [B*S,256] @ [256,256]^T
    mma_gemm_wt_bias<<<dim3(4, MB), blk>>>(enc, val_w, val_b, p_value, 256);
    // sampling offsets: N=192
    mma_gemm_wt_bias<<<dim3(3, MB), blk>>>(hidden, off_w, off_b, p_off, 192);
    // attention weights: N=96
    mma_gemm_wt_bias<<<dim3(2, MB), blk>>>(hidden, aw_w, aw_b, p_aw, 96);

    // deformable sampling: block = 8 queries x 8 heads
    msda_sample_kernel<<<MROWS / QB, blk>>>(refp);

    // output projection
    mma_gemm_wt_bias<<<dim3(4, MB), blk>>>(p_msda, out_w, out_b, out, 256);
}